// round 14
// baseline (speedup 1.0000x reference)
#include <cuda_runtime.h>
#include <cuda_fp16.h>
#include <cstdint>

#define NN 100000
#define DD 64
#define HH 256
#define EE 1000000

#define ROWS_TOTAL 200000            // geo rows [0,NN) + trans rows [NN,2NN)
#define TILE_M 128
#define NTILES 1563                  // ceil(200000/128)
#define ROWS_PAD (NTILES * TILE_M)   // 200064
#define NSEG (2 * NN)                // 200000 segments (geo + trans)
#define MLP_GRID 592                 // 4 CTAs/SM x 148 SMs — one wave
#define PGRID 296                    // prep kernel: 2 CTAs/SM, all resident
#define PCH 676                      // scan chunk per block: 296*676 >= NSEG

// ---------------- scratch (device globals; no allocs) ----------------
__device__ __align__(256) float g_z[ROWS_PAD * DD];   // geo-mean rows then trans rows
__device__ __align__(256) __half g_feath[NN * DD];    // fp16 copy of loc_feat
__device__ __align__(256) int   g_deg[NSEG];
__device__ __align__(256) int   g_rowptr[NSEG + 1];
__device__ __align__(256) int   g_cursor[NSEG];
__device__ __align__(256) int   g_esrc[EE];           // geo edges: src
__device__ __align__(256) int2  g_epair[EE];          // trans edges: (src, w)
__device__ int g_bsum[PGRID];
__device__ __align__(16)  float g_w[2];
__device__ unsigned g_done;
__device__ unsigned g_bar_count;
__device__ unsigned g_bar_gen;
__device__ __align__(256) __half g_w1h[HH * DD];      // W1^T fp16: [n][k]

#define SWZ128(o) ((o) ^ (((o) >> 3) & 0x70))

__device__ __forceinline__ uint32_t smem_u32(const void* p) {
    uint32_t a;
    asm("{ .reg .u64 t; cvta.to.shared.u64 t, %1; cvt.u32.u64 %0, t; }" : "=r"(a) : "l"(p));
    return a;
}

// ---------------- grid barrier for prep kernel (PGRID CTAs, all resident) ----
__device__ __forceinline__ void prep_bar() {
    __syncthreads();
    if (threadIdx.x == 0) {
        __threadfence();
        unsigned gen;
        asm volatile("ld.acquire.gpu.u32 %0, [%1];" : "=r"(gen) : "l"(&g_bar_gen));
        unsigned t = atomicAdd(&g_bar_count, 1u);
        if (t == PGRID - 1) {
            g_bar_count = 0;
            asm volatile("st.release.gpu.u32 [%0], %1;" :: "l"(&g_bar_gen), "r"(gen + 1) : "memory");
        } else {
            unsigned cur;
            do {
                asm volatile("ld.acquire.gpu.u32 %0, [%1];" : "=r"(cur) : "l"(&g_bar_gen));
            } while (cur == gen);
        }
    }
    __syncthreads();
}

// ---------------- prep: zero + feat->fp16 + W1->fp16 + hist + scan -----------
__global__ void __launch_bounds__(256, 2)
prep_kernel(const float* __restrict__ feat,
            const float* __restrict__ W1,
            const int* __restrict__ gdst,
            const int* __restrict__ tdst) {
    __shared__ int sb[512];
    __shared__ int s_base;
    int tid = threadIdx.x, bid = blockIdx.x;
    int gid = bid * 256 + tid;
    int gstride = PGRID * 256;

    // ===== phase A: zero; convert feat + W1^T to fp16 =====
    for (int i = gid; i < NSEG / 4; i += gstride)
        ((int4*)g_deg)[i] = make_int4(0, 0, 0, 0);
    if (gid < (ROWS_PAD - ROWS_TOTAL) * DD / 4)
        ((float4*)g_z)[ROWS_TOTAL * DD / 4 + gid] = make_float4(0.f, 0.f, 0.f, 0.f);
    if (gid == 0) { g_w[0] = 0.f; g_w[1] = 0.f; g_done = 0u; }
    for (int i = gid; i < NN * DD / 4; i += gstride) {      // feat -> fp16 (x4)
        float4 v = __ldg(&((const float4*)feat)[i]);
        __half2 h0 = __floats2half2_rn(v.x, v.y);
        __half2 h1 = __floats2half2_rn(v.z, v.w);
        ((uint2*)g_feath)[i] = make_uint2(*(uint32_t*)&h0, *(uint32_t*)&h1);
    }
    if (gid < HH * DD) {
        int n = gid >> 6, k = gid & 63;
        g_w1h[gid] = __float2half_rn(__ldg(&W1[k * HH + n]));
    }
    prep_bar();

    // ===== phase B: histogram of dst degrees =====
    for (int i = gid; i < 2 * EE; i += gstride) {
        if (i < EE) atomicAdd(&g_deg[__ldg(&gdst[i])], 1);
        else        atomicAdd(&g_deg[NN + __ldg(&tdst[i - EE])], 1);
    }
    prep_bar();

    // ===== phase C1: per-block chunk sums =====
    int cbase = bid * PCH;
    {
        int sum = 0;
        for (int i = tid; i < PCH; i += 256) {
            int idx = cbase + i;
            if (idx < NSEG) sum += g_deg[idx];
        }
        sb[tid] = sum; __syncthreads();
        for (int s = 128; s > 0; s >>= 1) {
            if (tid < s) sb[tid] += sb[tid + s];
            __syncthreads();
        }
        if (tid == 0) g_bsum[bid] = sb[0];
    }
    prep_bar();

    // ===== phase C2: every block scans the PGRID block sums (inclusive) =====
    {
        sb[tid]       = (tid < PGRID) ? g_bsum[tid] : 0;
        sb[tid + 256] = (tid + 256 < PGRID) ? g_bsum[tid + 256] : 0;
        __syncthreads();
        for (int off = 1; off < 512; off <<= 1) {
            int v0 = (tid >= off) ? sb[tid - off] : 0;
            int i1 = tid + 256;
            int v1 = (i1 >= off) ? sb[i1 - off] : 0;
            __syncthreads();
            sb[tid] += v0; sb[i1] += v1;
            __syncthreads();
        }
        if (tid == 0) s_base = sb[bid] - g_bsum[bid];   // exclusive base
        __syncthreads();
    }

    // ===== phase C3: local scan of own chunk (3 elements per thread) =====
    {
        int i0 = cbase + tid * 3;
        int v[3] = {0, 0, 0};
        #pragma unroll
        for (int j = 0; j < 3; j++) {
            int idx = i0 + j;
            if (tid * 3 + j < PCH && idx < NSEG) v[j] = g_deg[idx];
        }
        int tsum = v[0] + v[1] + v[2];
        sb[tid] = tsum; __syncthreads();
        for (int off = 1; off < 256; off <<= 1) {
            int x = (tid >= off) ? sb[tid - off] : 0;
            __syncthreads();
            sb[tid] += x;
            __syncthreads();
        }
        int run = s_base + sb[tid] - tsum;
        #pragma unroll
        for (int j = 0; j < 3; j++) {
            int idx = i0 + j;
            if (tid * 3 + j < PCH && idx < NSEG) {
                g_rowptr[idx] = run; g_cursor[idx] = run;
            }
            run += v[j];
        }
        if (bid == 0 && tid == 0) g_rowptr[NSEG] = 2 * EE;
    }
}

// ---------------- fill CSR edge arrays ----------------
__global__ void fill_kernel(const int* __restrict__ gsrc,
                            const int* __restrict__ gdst,
                            const int* __restrict__ tsrc,
                            const int* __restrict__ tdst,
                            const float* __restrict__ tw) {
    int i = blockIdx.x * blockDim.x + threadIdx.x;
    if (i >= 2 * EE) return;
    if (i < EE) {
        int d = __ldg(&gdst[i]);
        int pos = atomicAdd(&g_cursor[d], 1);
        g_esrc[pos] = __ldg(&gsrc[i]);
    } else {
        int j = i - EE;
        int d = NN + __ldg(&tdst[j]);
        int pos = atomicAdd(&g_cursor[d], 1);        // pos in [EE, 2EE)
        g_epair[pos - EE] = make_int2(__ldg(&tsrc[j]), __float_as_int(__ldg(&tw[j])));
    }
}

// ---------------- gather-SpMM over fp16 feat: one warp per segment -----------
__global__ void __launch_bounds__(256)
gather_kernel() {
    int gw = (blockIdx.x * blockDim.x + threadIdx.x) >> 5;  // 0 .. NSEG-1
    int lane = threadIdx.x & 31;
    if (gw >= NSEG) return;
    int start = g_rowptr[gw];
    int end   = g_rowptr[gw + 1];
    const __half2* f2 = (const __half2*)g_feath;    // row = 32 half2
    float ax = 0.f, ay = 0.f;

    if (gw < NN) {
        for (int jb = start; jb < end; jb += 32) {
            int n32 = min(32, end - jb);
            int e = (lane < n32) ? __ldg(&g_esrc[jb + lane]) : 0;
            int t = 0;
            for (; t + 4 <= n32; t += 4) {
                int s0 = __shfl_sync(0xFFFFFFFFu, e, t);
                int s1 = __shfl_sync(0xFFFFFFFFu, e, t + 1);
                int s2 = __shfl_sync(0xFFFFFFFFu, e, t + 2);
                int s3 = __shfl_sync(0xFFFFFFFFu, e, t + 3);
                float2 v0 = __half22float2(__ldg(&f2[s0 * 32 + lane]));
                float2 v1 = __half22float2(__ldg(&f2[s1 * 32 + lane]));
                float2 v2 = __half22float2(__ldg(&f2[s2 * 32 + lane]));
                float2 v3 = __half22float2(__ldg(&f2[s3 * 32 + lane]));
                ax += v0.x + v1.x + v2.x + v3.x;
                ay += v0.y + v1.y + v2.y + v3.y;
            }
            for (; t < n32; t++) {
                int s = __shfl_sync(0xFFFFFFFFu, e, t);
                float2 v = __half22float2(__ldg(&f2[s * 32 + lane]));
                ax += v.x; ay += v.y;
            }
        }
        int deg = end - start;
        float inv = (deg > 0) ? 1.f / (float)deg : 0.f;
        ax *= inv; ay *= inv;
    } else {
        for (int jb = start; jb < end; jb += 32) {
            int n32 = min(32, end - jb);
            int e = 0; float w = 0.f;
            if (lane < n32) {
                int2 p = __ldg(&g_epair[jb - EE + lane]);
                e = p.x; w = __int_as_float(p.y);
            }
            int t = 0;
            for (; t + 4 <= n32; t += 4) {
                int s0 = __shfl_sync(0xFFFFFFFFu, e, t);
                int s1 = __shfl_sync(0xFFFFFFFFu, e, t + 1);
                int s2 = __shfl_sync(0xFFFFFFFFu, e, t + 2);
                int s3 = __shfl_sync(0xFFFFFFFFu, e, t + 3);
                float w0 = __shfl_sync(0xFFFFFFFFu, w, t);
                float w1 = __shfl_sync(0xFFFFFFFFu, w, t + 1);
                float w2 = __shfl_sync(0xFFFFFFFFu, w, t + 2);
                float w3 = __shfl_sync(0xFFFFFFFFu, w, t + 3);
                float2 v0 = __half22float2(__ldg(&f2[s0 * 32 + lane]));
                float2 v1 = __half22float2(__ldg(&f2[s1 * 32 + lane]));
                float2 v2 = __half22float2(__ldg(&f2[s2 * 32 + lane]));
                float2 v3 = __half22float2(__ldg(&f2[s3 * 32 + lane]));
                ax += v0.x * w0 + v1.x * w1 + v2.x * w2 + v3.x * w3;
                ay += v0.y * w0 + v1.y * w1 + v2.y * w2 + v3.y * w3;
            }
            for (; t < n32; t++) {
                int s  = __shfl_sync(0xFFFFFFFFu, e, t);
                float ww = __shfl_sync(0xFFFFFFFFu, w, t);
                float2 v = __half22float2(__ldg(&f2[s * 32 + lane]));
                ax += v.x * ww; ay += v.y * ww;
            }
        }
    }
    float2 o; o.x = ax; o.y = ay;
    ((float2*)g_z)[gw * 32 + lane] = o;
}

// ---------------- MMA helpers (fp16 single-term) ----------------
__device__ __forceinline__ uint32_t pack_h2(float lo, float hi) {
    __half2 h = __floats2half2_rn(lo, hi);   // .x = low half
    return *(uint32_t*)&h;
}
__device__ __forceinline__ void mma_f16(float& c0, float& c1, float& c2, float& c3,
                                        uint32_t a0, uint32_t a1, uint32_t a2, uint32_t a3,
                                        uint32_t b0, uint32_t b1) {
    asm volatile(
        "mma.sync.aligned.m16n8k16.row.col.f32.f16.f16.f32 "
        "{%0,%1,%2,%3}, {%4,%5,%6,%7}, {%8,%9}, {%0,%1,%2,%3};"
        : "+f"(c0), "+f"(c1), "+f"(c2), "+f"(c3)
        : "r"(a0), "r"(a1), "r"(a2), "r"(a3), "r"(b0), "r"(b1));
}
__device__ __forceinline__ void ldsm_x4(uint32_t& r0, uint32_t& r1, uint32_t& r2, uint32_t& r3,
                                        uint32_t addr) {
    asm volatile("ldmatrix.sync.aligned.m8n8.x4.shared.b16 {%0,%1,%2,%3}, [%4];"
                 : "=r"(r0), "=r"(r1), "=r"(r2), "=r"(r3) : "r"(addr));
}
__device__ __forceinline__ float tanh_fast(float x) {
    float h;
    asm("tanh.approx.f32 %0, %1;" : "=f"(h) : "f"(x));
    return h;
}

// ---------------- MLP: persistent fp16 HMMA GEMM + logits + barrier + blend --
#define SB_W 0
#define OFF_RED 32768
#define MLP_SMEM (32768 + 64)

extern __shared__ char msmem[];
__global__ void __launch_bounds__(128, 4)
mlp_kernel(const float* __restrict__ b1, const float* __restrict__ W2,
           float* __restrict__ out) {
    uint32_t sbase = smem_u32(msmem);
    float* red = (float*)(msmem + OFF_RED);
    int tid = threadIdx.x;
    int wid = tid >> 5, lid = tid & 31;
    int q = lid & 3;

    // Stage W1^T fp16 into SW128-swizzled smem once per block: 256 rows x 128B
    {
        const uint4* sw1 = (const uint4*)g_w1h;
        #pragma unroll
        for (int i = 0; i < 16; i++) {
            int idx = i * 128 + tid;            // 2048 uint4
            int o = idx * 16;
            int sw = SWZ128(o);
            *(uint4*)(msmem + SB_W + sw) = sw1[idx];
        }
    }
    __syncthreads();

    int rl = lid & 7;
    int quad = lid >> 3;
    int off0 = rl * 128 + (((quad)     ^ rl) << 4);
    int off1 = rl * 128 + (((quad + 4) ^ rl) << 4);

    float sg = 0.f, st = 0.f;    // per-warp logit accumulators (geo / trans)

    for (int tile = blockIdx.x; tile < NTILES; tile += gridDim.x) {
        int base = tile * TILE_M + wid * 32;

        // A fragments (fp16) from fp32 g_z
        uint32_t A[2][4][4];
        #pragma unroll
        for (int t = 0; t < 2; t++) {
            int ra = base + t * 16 + (lid >> 2);
            const float* pa = g_z + (size_t)ra * DD;
            const float* pb = pa + 8 * DD;
            #pragma unroll
            for (int kc = 0; kc < 4; kc++) {
                int k0 = kc * 16 + q * 2;
                float2 v0 = __ldg((const float2*)(pa + k0));
                float2 v1 = __ldg((const float2*)(pb + k0));
                float2 v2 = __ldg((const float2*)(pa + k0 + 8));
                float2 v3 = __ldg((const float2*)(pb + k0 + 8));
                A[t][kc][0] = pack_h2(v0.x, v0.y);
                A[t][kc][1] = pack_h2(v1.x, v1.y);
                A[t][kc][2] = pack_h2(v2.x, v2.y);
                A[t][kc][3] = pack_h2(v3.x, v3.y);
            }
        }

        float p00 = 0.f, p01 = 0.f, p10 = 0.f, p11 = 0.f;

        #pragma unroll 4
        for (int nc = 0; nc < 32; nc++) {
            uint32_t nb = nc * 1024;
            uint32_t bh[4][2];
            ldsm_x4(bh[0][0], bh[0][1], bh[1][0], bh[1][1], sbase + SB_W + nb + off0);
            ldsm_x4(bh[2][0], bh[2][1], bh[3][0], bh[3][1], sbase + SB_W + nb + off1);

            int col0 = nc * 8 + q * 2;
            float2 b1v = __ldg((const float2*)(b1 + col0));
            float2 w2v = __ldg((const float2*)(W2 + col0));

            #pragma unroll
            for (int t = 0; t < 2; t++) {
                float c0 = 0.f, c1 = 0.f, c2 = 0.f, c3 = 0.f;
                #pragma unroll
                for (int kc = 0; kc < 4; kc++) {
                    mma_f16(c0, c1, c2, c3,
                            A[t][kc][0], A[t][kc][1], A[t][kc][2], A[t][kc][3],
                            bh[kc][0], bh[kc][1]);
                }
                float u = tanh_fast(c0 + b1v.x) * w2v.x + tanh_fast(c1 + b1v.y) * w2v.y;
                float v = tanh_fast(c2 + b1v.x) * w2v.x + tanh_fast(c3 + b1v.y) * w2v.y;
                if (t == 0) { p00 += u; p01 += v; } else { p10 += u; p11 += v; }
            }
        }

        int r00 = base + (lid >> 2);
        float s = 0.f;
        if (r00      < ROWS_TOTAL) s += p00;
        if (r00 + 8  < ROWS_TOTAL) s += p01;
        if (r00 + 16 < ROWS_TOTAL) s += p10;
        if (r00 + 24 < ROWS_TOTAL) s += p11;
        if (base < NN) sg += s; else st += s;   // NN % 32 == 0 -> warp-uniform
    }

    #pragma unroll
    for (int sh = 16; sh > 0; sh >>= 1) {
        sg += __shfl_xor_sync(0xFFFFFFFFu, sg, sh);
        st += __shfl_xor_sync(0xFFFFFFFFu, st, sh);
    }
    if (lid == 0) { red[wid * 2] = sg; red[wid * 2 + 1] = st; }
    __syncthreads();

    // --- grid barrier: publish logits, wait for all CTAs ---
    if (tid == 0) {
        float s0 = red[0] + red[2] + red[4] + red[6];
        float s1 = red[1] + red[3] + red[5] + red[7];
        atomicAdd(&g_w[0], s0);
        atomicAdd(&g_w[1], s1);
        __threadfence();
        atomicAdd(&g_done, 1u);
        unsigned v;
        do {
            asm volatile("ld.acquire.gpu.u32 %0, [%1];" : "=r"(v) : "l"(&g_done));
        } while (v < (unsigned)MLP_GRID);
        float w0, w1;
        asm volatile("ld.acquire.gpu.f32 %0, [%1];" : "=f"(w0) : "l"(&g_w[0]));
        asm volatile("ld.acquire.gpu.f32 %0, [%1];" : "=f"(w1) : "l"(&g_w[1]));
        w0 *= (1.0f / NN); w1 *= (1.0f / NN);
        float beta0 = 1.f / (1.f + expf(w1 - w0));
        red[0] = beta0;
        red[1] = 1.f - beta0;
    }
    __syncthreads();
    float beta0 = red[0], beta1 = red[1];

    // --- fused blend: out = beta0*geo_mean + beta1*trans ---
    int total = NN * 16;                           // float4 count
    for (int idx = blockIdx.x * 128 + tid; idx < total; idx += gridDim.x * 128) {
        float4 a = ((const float4*)g_z)[idx];
        float4 b = ((const float4*)g_z)[NN * 16 + idx];
        float4 o;
        o.x = beta0 * a.x + beta1 * b.x;
        o.y = beta0 * a.y + beta1 * b.y;
        o.z = beta0 * a.z + beta1 * b.z;
        o.w = beta0 * a.w + beta1 * b.w;
        ((float4*)out)[idx] = o;
    }
}

// ---------------- launch ----------------
extern "C" void kernel_launch(void* const* d_in, const int* in_sizes, int n_in,
                              void* d_out, int out_size) {
    const float* feat = (const float*)d_in[0];
    const int*   gsrc = (const int*)d_in[1];
    const int*   gdst = (const int*)d_in[2];
    const int*   tsrc = (const int*)d_in[3];
    const int*   tdst = (const int*)d_in[4];
    const float* tw   = (const float*)d_in[5];
    const float* W1   = (const float*)d_in[6];
    const float* b1   = (const float*)d_in[7];
    const float* W2   = (const float*)d_in[8];
    float* out = (float*)d_out;

    prep_kernel<<<PGRID, 256>>>(feat, W1, gdst, tdst);
    fill_kernel<<<(2 * EE + 255) / 256, 256>>>(gsrc, gdst, tsrc, tdst, tw);
    gather_kernel<<<(NSEG + 7) / 8, 256>>>();

    cudaFuncSetAttribute(mlp_kernel, cudaFuncAttributeMaxDynamicSharedMemorySize, MLP_SMEM);
    mlp_kernel<<<MLP_GRID, 128, MLP_SMEM>>>(b1, W2, out);
}

// round 15
// speedup vs baseline: 1.2973x; 1.2973x over previous
#include <cuda_runtime.h>
#include <cuda_fp16.h>
#include <cstdint>

#define NN 100000
#define DD 64
#define HH 256
#define EE 1000000

#define ROWS_TOTAL 200000            // geo rows [0,NN) + trans rows [NN,2NN)
#define TILE_M 128
#define NTILES 1563                  // ceil(200000/128)
#define ROWS_PAD (NTILES * TILE_M)   // 200064
#define NSEG (2 * NN)                // 200000 segments (geo + trans)
#define MLP_GRID 444                 // 3 CTAs/SM x 148 SMs — proven-best mlp config
#define PGRID 296                    // prep kernel: 2 CTAs/SM, all resident
#define PCH 676                      // scan chunk per block: 296*676 >= NSEG

// ---------------- scratch (device globals; no allocs) ----------------
__device__ __align__(256) float g_z[ROWS_PAD * DD];   // geo-mean rows then trans rows
__device__ __align__(256) __half g_feath[NN * DD];    // fp16 copy of loc_feat
__device__ __align__(256) int   g_deg[NSEG];
__device__ __align__(256) int   g_rowptr[NSEG + 1];
__device__ __align__(256) int   g_cursor[NSEG];
__device__ __align__(256) int   g_esrc[EE];           // geo edges: src
__device__ __align__(256) int2  g_epair[EE];          // trans edges: (src, w)
__device__ int g_bsum[PGRID];
__device__ __align__(16)  float g_w[2];
__device__ unsigned g_done;
__device__ unsigned g_bar_count;
__device__ unsigned g_bar_gen;
__device__ __align__(256) __half g_w1h[HH * DD];      // W1^T fp16: [n][k]

#define SWZ128(o) ((o) ^ (((o) >> 3) & 0x70))

__device__ __forceinline__ uint32_t smem_u32(const void* p) {
    uint32_t a;
    asm("{ .reg .u64 t; cvta.to.shared.u64 t, %1; cvt.u32.u64 %0, t; }" : "=r"(a) : "l"(p));
    return a;
}

// ---------------- grid barrier for prep kernel (PGRID CTAs, all resident) ----
__device__ __forceinline__ void prep_bar() {
    __syncthreads();
    if (threadIdx.x == 0) {
        __threadfence();
        unsigned gen;
        asm volatile("ld.acquire.gpu.u32 %0, [%1];" : "=r"(gen) : "l"(&g_bar_gen));
        unsigned t = atomicAdd(&g_bar_count, 1u);
        if (t == PGRID - 1) {
            g_bar_count = 0;
            asm volatile("st.release.gpu.u32 [%0], %1;" :: "l"(&g_bar_gen), "r"(gen + 1) : "memory");
        } else {
            unsigned cur;
            do {
                asm volatile("ld.acquire.gpu.u32 %0, [%1];" : "=r"(cur) : "l"(&g_bar_gen));
            } while (cur == gen);
        }
    }
    __syncthreads();
}

// ---------------- prep: zero + feat->fp16 + W1->fp16 + hist + scan -----------
__global__ void __launch_bounds__(256, 2)
prep_kernel(const float* __restrict__ feat,
            const float* __restrict__ W1,
            const int* __restrict__ gdst,
            const int* __restrict__ tdst) {
    __shared__ int sb[512];
    __shared__ int s_base;
    int tid = threadIdx.x, bid = blockIdx.x;
    int gid = bid * 256 + tid;
    int gstride = PGRID * 256;

    // ===== phase A: zero; convert feat + W1^T to fp16 =====
    for (int i = gid; i < NSEG / 4; i += gstride)
        ((int4*)g_deg)[i] = make_int4(0, 0, 0, 0);
    if (gid < (ROWS_PAD - ROWS_TOTAL) * DD / 4)
        ((float4*)g_z)[ROWS_TOTAL * DD / 4 + gid] = make_float4(0.f, 0.f, 0.f, 0.f);
    if (gid == 0) { g_w[0] = 0.f; g_w[1] = 0.f; g_done = 0u; }
    for (int i = gid; i < NN * DD / 4; i += gstride) {      // feat -> fp16 (x4)
        float4 v = __ldg(&((const float4*)feat)[i]);
        __half2 h0 = __floats2half2_rn(v.x, v.y);
        __half2 h1 = __floats2half2_rn(v.z, v.w);
        ((uint2*)g_feath)[i] = make_uint2(*(uint32_t*)&h0, *(uint32_t*)&h1);
    }
    if (gid < HH * DD) {
        int n = gid >> 6, k = gid & 63;
        g_w1h[gid] = __float2half_rn(__ldg(&W1[k * HH + n]));
    }
    prep_bar();

    // ===== phase B: histogram of dst degrees =====
    for (int i = gid; i < 2 * EE; i += gstride) {
        if (i < EE) atomicAdd(&g_deg[__ldg(&gdst[i])], 1);
        else        atomicAdd(&g_deg[NN + __ldg(&tdst[i - EE])], 1);
    }
    prep_bar();

    // ===== phase C1: per-block chunk sums =====
    int cbase = bid * PCH;
    {
        int sum = 0;
        for (int i = tid; i < PCH; i += 256) {
            int idx = cbase + i;
            if (idx < NSEG) sum += g_deg[idx];
        }
        sb[tid] = sum; __syncthreads();
        for (int s = 128; s > 0; s >>= 1) {
            if (tid < s) sb[tid] += sb[tid + s];
            __syncthreads();
        }
        if (tid == 0) g_bsum[bid] = sb[0];
    }
    prep_bar();

    // ===== phase C2: every block scans the PGRID block sums (inclusive) =====
    {
        sb[tid]       = (tid < PGRID) ? g_bsum[tid] : 0;
        sb[tid + 256] = (tid + 256 < PGRID) ? g_bsum[tid + 256] : 0;
        __syncthreads();
        for (int off = 1; off < 512; off <<= 1) {
            int v0 = (tid >= off) ? sb[tid - off] : 0;
            int i1 = tid + 256;
            int v1 = (i1 >= off) ? sb[i1 - off] : 0;
            __syncthreads();
            sb[tid] += v0; sb[i1] += v1;
            __syncthreads();
        }
        if (tid == 0) s_base = sb[bid] - g_bsum[bid];   // exclusive base
        __syncthreads();
    }

    // ===== phase C3: local scan of own chunk (3 elements per thread) =====
    {
        int i0 = cbase + tid * 3;
        int v[3] = {0, 0, 0};
        #pragma unroll
        for (int j = 0; j < 3; j++) {
            int idx = i0 + j;
            if (tid * 3 + j < PCH && idx < NSEG) v[j] = g_deg[idx];
        }
        int tsum = v[0] + v[1] + v[2];
        sb[tid] = tsum; __syncthreads();
        for (int off = 1; off < 256; off <<= 1) {
            int x = (tid >= off) ? sb[tid - off] : 0;
            __syncthreads();
            sb[tid] += x;
            __syncthreads();
        }
        int run = s_base + sb[tid] - tsum;
        #pragma unroll
        for (int j = 0; j < 3; j++) {
            int idx = i0 + j;
            if (tid * 3 + j < PCH && idx < NSEG) {
                g_rowptr[idx] = run; g_cursor[idx] = run;
            }
            run += v[j];
        }
        if (bid == 0 && tid == 0) g_rowptr[NSEG] = 2 * EE;
    }
}

// ---------------- fill CSR edge arrays ----------------
__global__ void fill_kernel(const int* __restrict__ gsrc,
                            const int* __restrict__ gdst,
                            const int* __restrict__ tsrc,
                            const int* __restrict__ tdst,
                            const float* __restrict__ tw) {
    int i = blockIdx.x * blockDim.x + threadIdx.x;
    if (i >= 2 * EE) return;
    if (i < EE) {
        int d = __ldg(&gdst[i]);
        int pos = atomicAdd(&g_cursor[d], 1);
        g_esrc[pos] = __ldg(&gsrc[i]);
    } else {
        int j = i - EE;
        int d = NN + __ldg(&tdst[j]);
        int pos = atomicAdd(&g_cursor[d], 1);        // pos in [EE, 2EE)
        g_epair[pos - EE] = make_int2(__ldg(&tsrc[j]), __float_as_int(__ldg(&tw[j])));
    }
}

// ---------------- gather-SpMM over fp16 feat: one warp per segment -----------
__global__ void __launch_bounds__(256)
gather_kernel() {
    int gw = (blockIdx.x * blockDim.x + threadIdx.x) >> 5;  // 0 .. NSEG-1
    int lane = threadIdx.x & 31;
    if (gw >= NSEG) return;
    int start = g_rowptr[gw];
    int end   = g_rowptr[gw + 1];
    const __half2* f2 = (const __half2*)g_feath;    // row = 32 half2 = 128B
    float ax = 0.f, ay = 0.f;

    if (gw < NN) {
        for (int jb = start; jb < end; jb += 32) {
            int n32 = min(32, end - jb);
            int e = (lane < n32) ? __ldg(&g_esrc[jb + lane]) : 0;
            int t = 0;
            for (; t + 4 <= n32; t += 4) {
                int s0 = __shfl_sync(0xFFFFFFFFu, e, t);
                int s1 = __shfl_sync(0xFFFFFFFFu, e, t + 1);
                int s2 = __shfl_sync(0xFFFFFFFFu, e, t + 2);
                int s3 = __shfl_sync(0xFFFFFFFFu, e, t + 3);
                float2 v0 = __half22float2(__ldg(&f2[s0 * 32 + lane]));
                float2 v1 = __half22float2(__ldg(&f2[s1 * 32 + lane]));
                float2 v2 = __half22float2(__ldg(&f2[s2 * 32 + lane]));
                float2 v3 = __half22float2(__ldg(&f2[s3 * 32 + lane]));
                ax += v0.x + v1.x + v2.x + v3.x;
                ay += v0.y + v1.y + v2.y + v3.y;
            }
            for (; t < n32; t++) {
                int s = __shfl_sync(0xFFFFFFFFu, e, t);
                float2 v = __half22float2(__ldg(&f2[s * 32 + lane]));
                ax += v.x; ay += v.y;
            }
        }
        int deg = end - start;
        float inv = (deg > 0) ? 1.f / (float)deg : 0.f;
        ax *= inv; ay *= inv;
    } else {
        for (int jb = start; jb < end; jb += 32) {
            int n32 = min(32, end - jb);
            int e = 0; float w = 0.f;
            if (lane < n32) {
                int2 p = __ldg(&g_epair[jb - EE + lane]);
                e = p.x; w = __int_as_float(p.y);
            }
            int t = 0;
            for (; t + 4 <= n32; t += 4) {
                int s0 = __shfl_sync(0xFFFFFFFFu, e, t);
                int s1 = __shfl_sync(0xFFFFFFFFu, e, t + 1);
                int s2 = __shfl_sync(0xFFFFFFFFu, e, t + 2);
                int s3 = __shfl_sync(0xFFFFFFFFu, e, t + 3);
                float w0 = __shfl_sync(0xFFFFFFFFu, w, t);
                float w1 = __shfl_sync(0xFFFFFFFFu, w, t + 1);
                float w2 = __shfl_sync(0xFFFFFFFFu, w, t + 2);
                float w3 = __shfl_sync(0xFFFFFFFFu, w, t + 3);
                float2 v0 = __half22float2(__ldg(&f2[s0 * 32 + lane]));
                float2 v1 = __half22float2(__ldg(&f2[s1 * 32 + lane]));
                float2 v2 = __half22float2(__ldg(&f2[s2 * 32 + lane]));
                float2 v3 = __half22float2(__ldg(&f2[s3 * 32 + lane]));
                ax += v0.x * w0 + v1.x * w1 + v2.x * w2 + v3.x * w3;
                ay += v0.y * w0 + v1.y * w1 + v2.y * w2 + v3.y * w3;
            }
            for (; t < n32; t++) {
                int s  = __shfl_sync(0xFFFFFFFFu, e, t);
                float ww = __shfl_sync(0xFFFFFFFFu, w, t);
                float2 v = __half22float2(__ldg(&f2[s * 32 + lane]));
                ax += v.x * ww; ay += v.y * ww;
            }
        }
    }
    float2 o; o.x = ax; o.y = ay;
    ((float2*)g_z)[gw * 32 + lane] = o;
}

// ---------------- MMA helpers (fp16 single-term) ----------------
__device__ __forceinline__ uint32_t pack_h2(float lo, float hi) {
    __half2 h = __floats2half2_rn(lo, hi);   // .x = low half
    return *(uint32_t*)&h;
}
__device__ __forceinline__ void mma_f16(float& c0, float& c1, float& c2, float& c3,
                                        uint32_t a0, uint32_t a1, uint32_t a2, uint32_t a3,
                                        uint32_t b0, uint32_t b1) {
    asm volatile(
        "mma.sync.aligned.m16n8k16.row.col.f32.f16.f16.f32 "
        "{%0,%1,%2,%3}, {%4,%5,%6,%7}, {%8,%9}, {%0,%1,%2,%3};"
        : "+f"(c0), "+f"(c1), "+f"(c2), "+f"(c3)
        : "r"(a0), "r"(a1), "r"(a2), "r"(a3), "r"(b0), "r"(b1));
}
__device__ __forceinline__ void ldsm_x4(uint32_t& r0, uint32_t& r1, uint32_t& r2, uint32_t& r3,
                                        uint32_t addr) {
    asm volatile("ldmatrix.sync.aligned.m8n8.x4.shared.b16 {%0,%1,%2,%3}, [%4];"
                 : "=r"(r0), "=r"(r1), "=r"(r2), "=r"(r3) : "r"(addr));
}
__device__ __forceinline__ float tanh_fast(float x) {
    float h;
    asm("tanh.approx.f32 %0, %1;" : "=f"(h) : "f"(x));
    return h;
}

// ---------------- MLP: persistent fp16 HMMA GEMM + logits + barrier + blend --
// Config pinned to the r12 measured-best point: grid 444, 128 thr, 3 CTAs/SM.
#define SB_W 0
#define OFF_RED 32768
#define MLP_SMEM (32768 + 64)

extern __shared__ char msmem[];
__global__ void __launch_bounds__(128, 3)
mlp_kernel(const float* __restrict__ b1, const float* __restrict__ W2,
           float* __restrict__ out) {
    uint32_t sbase = smem_u32(msmem);
    float* red = (float*)(msmem + OFF_RED);
    int tid = threadIdx.x;
    int wid = tid >> 5, lid = tid & 31;
    int q = lid & 3;

    // Stage W1^T fp16 into SW128-swizzled smem once per block: 256 rows x 128B
    {
        const uint4* sw1 = (const uint4*)g_w1h;
        #pragma unroll
        for (int i = 0; i < 16; i++) {
            int idx = i * 128 + tid;            // 2048 uint4
            int o = idx * 16;
            int sw = SWZ128(o);
            *(uint4*)(msmem + SB_W + sw) = sw1[idx];
        }
    }
    __syncthreads();

    int rl = lid & 7;
    int quad = lid >> 3;
    int off0 = rl * 128 + (((quad)     ^ rl) << 4);
    int off1 = rl * 128 + (((quad + 4) ^ rl) << 4);

    float sg = 0.f, st = 0.f;    // per-warp logit accumulators (geo / trans)

    for (int tile = blockIdx.x; tile < NTILES; tile += gridDim.x) {
        int base = tile * TILE_M + wid * 32;

        // A fragments (fp16) from fp32 g_z
        uint32_t A[2][4][4];
        #pragma unroll
        for (int t = 0; t < 2; t++) {
            int ra = base + t * 16 + (lid >> 2);
            const float* pa = g_z + (size_t)ra * DD;
            const float* pb = pa + 8 * DD;
            #pragma unroll
            for (int kc = 0; kc < 4; kc++) {
                int k0 = kc * 16 + q * 2;
                float2 v0 = __ldg((const float2*)(pa + k0));
                float2 v1 = __ldg((const float2*)(pb + k0));
                float2 v2 = __ldg((const float2*)(pa + k0 + 8));
                float2 v3 = __ldg((const float2*)(pb + k0 + 8));
                A[t][kc][0] = pack_h2(v0.x, v0.y);
                A[t][kc][1] = pack_h2(v1.x, v1.y);
                A[t][kc][2] = pack_h2(v2.x, v2.y);
                A[t][kc][3] = pack_h2(v3.x, v3.y);
            }
        }

        float p00 = 0.f, p01 = 0.f, p10 = 0.f, p11 = 0.f;

        #pragma unroll 4
        for (int nc = 0; nc < 32; nc++) {
            uint32_t nb = nc * 1024;
            uint32_t bh[4][2];
            ldsm_x4(bh[0][0], bh[0][1], bh[1][0], bh[1][1], sbase + SB_W + nb + off0);
            ldsm_x4(bh[2][0], bh[2][1], bh[3][0], bh[3][1], sbase + SB_W + nb + off1);

            int col0 = nc * 8 + q * 2;
            float2 b1v = __ldg((const float2*)(b1 + col0));
            float2 w2v = __ldg((const float2*)(W2 + col0));

            #pragma unroll
            for (int t = 0; t < 2; t++) {
                float c0 = 0.f, c1 = 0.f, c2 = 0.f, c3 = 0.f;
                #pragma unroll
                for (int kc = 0; kc < 4; kc++) {
                    mma_f16(c0, c1, c2, c3,
                            A[t][kc][0], A[t][kc][1], A[t][kc][2], A[t][kc][3],
                            bh[kc][0], bh[kc][1]);
                }
                float u = tanh_fast(c0 + b1v.x) * w2v.x + tanh_fast(c1 + b1v.y) * w2v.y;
                float v = tanh_fast(c2 + b1v.x) * w2v.x + tanh_fast(c3 + b1v.y) * w2v.y;
                if (t == 0) { p00 += u; p01 += v; } else { p10 += u; p11 += v; }
            }
        }

        int r00 = base + (lid >> 2);
        float s = 0.f;
        if (r00      < ROWS_TOTAL) s += p00;
        if (r00 + 8  < ROWS_TOTAL) s += p01;
        if (r00 + 16 < ROWS_TOTAL) s += p10;
        if (r00 + 24 < ROWS_TOTAL) s += p11;
        if (base < NN) sg += s; else st += s;   // NN % 32 == 0 -> warp-uniform
    }

    #pragma unroll
    for (int sh = 16; sh > 0; sh >>= 1) {
        sg += __shfl_xor_sync(0xFFFFFFFFu, sg, sh);
        st += __shfl_xor_sync(0xFFFFFFFFu, st, sh);
    }
    if (lid == 0) { red[wid * 2] = sg; red[wid * 2 + 1] = st; }
    __syncthreads();

    // --- grid barrier: publish logits, wait for all CTAs ---
    if (tid == 0) {
        float s0 = red[0] + red[2] + red[4] + red[6];
        float s1 = red[1] + red[3] + red[5] + red[7];
        atomicAdd(&g_w[0], s0);
        atomicAdd(&g_w[1], s1);
        __threadfence();
        atomicAdd(&g_done, 1u);
        unsigned v;
        do {
            asm volatile("ld.acquire.gpu.u32 %0, [%1];" : "=r"(v) : "l"(&g_done));
        } while (v < (unsigned)MLP_GRID);
        float w0, w1;
        asm volatile("ld.acquire.gpu.f32 %0, [%1];" : "=f"(w0) : "l"(&g_w[0]));
        asm volatile("ld.acquire.gpu.f32 %0, [%1];" : "=f"(w1) : "l"(&g_w[1]));
        w0 *= (1.0f / NN); w1 *= (1.0f / NN);
        float beta0 = 1.f / (1.f + expf(w1 - w0));
        red[0] = beta0;
        red[1] = 1.f - beta0;
    }
    __syncthreads();
    float beta0 = red[0], beta1 = red[1];

    // --- fused blend: out = beta0*geo_mean + beta1*trans ---
    int total = NN * 16;                           // float4 count
    for (int idx = blockIdx.x * 128 + tid; idx < total; idx += gridDim.x * 128) {
        float4 a = ((const float4*)g_z)[idx];
        float4 b = ((const float4*)g_z)[NN * 16 + idx];
        float4 o;
        o.x = beta0 * a.x + beta1 * b.x;
        o.y = beta0 * a.y + beta1 * b.y;
        o.z = beta0 * a.z + beta1 * b.z;
        o.w = beta0 * a.w + beta1 * b.w;
        ((float4*)out)[idx] = o;
    }
}

// ---------------- launch ----------------
extern "C" void kernel_launch(void* const* d_in, const int* in_sizes, int n_in,
                              void* d_out, int out_size) {
    const float* feat = (const float*)d_in[0];
    const int*   gsrc = (const int*)d_in[1];
    const int*   gdst = (const int*)d_in[2];
    const int*   tsrc = (const int*)d_in[3];
    const int*   tdst = (const int*)d_in[4];
    const float* tw   = (const float*)d_in[5];
    const float* W1   = (const float*)d_in[6];
    const float* b1   = (const float*)d_in[7];
    const float* W2   = (const float*)d_in[8];
    float* out = (float*)d_out;

    prep_kernel<<<PGRID, 256>>>(feat, W1, gdst, tdst);
    fill_kernel<<<(2 * EE + 255) / 256, 256>>>(gsrc, gdst, tsrc, tdst, tw);
    gather_kernel<<<(NSEG + 7) / 8, 256>>>();

    cudaFuncSetAttribute(mlp_kernel, cudaFuncAttributeMaxDynamicSharedMemorySize, MLP_SMEM);
    mlp_kernel<<<MLP_GRID, 128, MLP_SMEM>>>(b1, W2, out);
}